// round 2
// baseline (speedup 1.0000x reference)
#include <cuda_runtime.h>
#include <cfloat>
#include <cstdint>

// Problem shape (fixed for this bench instance)
constexpr int NB  = 16;     // batch
constexpr int SEQ = 2048;   // sequence
constexpr int HD  = 128;    // head dim
constexpr int TT  = SEQ / 128;            // 16 tiles per axis
constexpr int NPAIRS = TT * (TT + 1) / 2; // 136 upper-tri tile pairs
#define SCALE 0.08838834764831845f        // 1/sqrt(128)

// Row softmax stats (device globals: no allocation allowed)
__device__ float g_m[NB * SEQ];
__device__ float g_linv[NB * SEQ];

// ---------------------------------------------------------------------------
// Kernel 1: raw scores GEMM.  s[b,i,j] = (K[b,i,:] . Q[b,j,:]) * SCALE
// Only tiles with jt >= it are computed (others are fully masked -> zero later).
// Written into the weights region of d_out as scratch.
// ---------------------------------------------------------------------------
__global__ __launch_bounds__(256) void scores_kernel(
    const float* __restrict__ Qg, const float* __restrict__ Kg,
    float* __restrict__ W)
{
    // decode (it, jt) with jt >= it from linear tile id
    int t = blockIdx.x;
    int b = blockIdx.y;
    int it = 0;
    while (true) { int len = TT - it; if (t < len) break; t -= len; ++it; }
    int jt = it + t;

    extern __shared__ float sm[];
    float* As = sm;              // [128][128]  As[d][i]  (K tile, transposed)
    float* Bs = sm + 128 * 128;  // [128][128]  Bs[d][j]  (Q tile, transposed)

    int tid = threadIdx.x;
    const float* Kbase = Kg + ((size_t)b * SEQ + (size_t)it * 128) * HD;
    const float* Qbase = Qg + ((size_t)b * SEQ + (size_t)jt * 128) * HD;

    // Load both 128x128 tiles transposed into smem.
    // Warp lanes -> 32 consecutive rows, same c4: smem stores are conflict-free.
    #pragma unroll
    for (int k = 0; k < 16; k++) {
        int idx = tid + k * 256;
        int row = idx & 127;
        int c4  = idx >> 7;           // 0..31
        float4 kv = *(const float4*)(Kbase + row * HD + c4 * 4);
        float4 qv = *(const float4*)(Qbase + row * HD + c4 * 4);
        As[(c4 * 4 + 0) * 128 + row] = kv.x;
        As[(c4 * 4 + 1) * 128 + row] = kv.y;
        As[(c4 * 4 + 2) * 128 + row] = kv.z;
        As[(c4 * 4 + 3) * 128 + row] = kv.w;
        Bs[(c4 * 4 + 0) * 128 + row] = qv.x;
        Bs[(c4 * 4 + 1) * 128 + row] = qv.y;
        Bs[(c4 * 4 + 2) * 128 + row] = qv.z;
        Bs[(c4 * 4 + 3) * 128 + row] = qv.w;
    }
    __syncthreads();

    int tx = tid & 15;   // j direction
    int ty = tid >> 4;   // i direction
    float c[8][8];
    #pragma unroll
    for (int a = 0; a < 8; a++)
        #pragma unroll
        for (int bq = 0; bq < 8; bq++) c[a][bq] = 0.f;

    #pragma unroll 8
    for (int d = 0; d < 128; d++) {
        float4 a0 = *(const float4*)(As + d * 128 + ty * 4);
        float4 a1 = *(const float4*)(As + d * 128 + 64 + ty * 4);
        float4 b0 = *(const float4*)(Bs + d * 128 + tx * 4);
        float4 b1 = *(const float4*)(Bs + d * 128 + 64 + tx * 4);
        float av[8] = {a0.x, a0.y, a0.z, a0.w, a1.x, a1.y, a1.z, a1.w};
        float bv[8] = {b0.x, b0.y, b0.z, b0.w, b1.x, b1.y, b1.z, b1.w};
        #pragma unroll
        for (int ri = 0; ri < 8; ri++)
            #pragma unroll
            for (int rj = 0; rj < 8; rj++)
                c[ri][rj] += av[ri] * bv[rj];
    }

    size_t Wbb = (size_t)b * SEQ * SEQ;
    #pragma unroll
    for (int ri = 0; ri < 8; ri++) {
        int i = it * 128 + ((ri < 4) ? (ty * 4 + ri) : (64 + ty * 4 + ri - 4));
        float* wrow = W + Wbb + (size_t)i * SEQ + jt * 128;
        float4 w0 = make_float4(c[ri][0] * SCALE, c[ri][1] * SCALE,
                                c[ri][2] * SCALE, c[ri][3] * SCALE);
        float4 w1 = make_float4(c[ri][4] * SCALE, c[ri][5] * SCALE,
                                c[ri][6] * SCALE, c[ri][7] * SCALE);
        *(float4*)(wrow + tx * 4)      = w0;
        *(float4*)(wrow + 64 + tx * 4) = w1;
    }
}

// ---------------------------------------------------------------------------
// Kernel 2: per-row softmax stats over j in [i, SEQ).
// ---------------------------------------------------------------------------
__global__ __launch_bounds__(128) void stats_kernel(const float* __restrict__ W)
{
    int row = blockIdx.x;            // b*SEQ + i
    int i = row & (SEQ - 1);
    const float* p = W + (size_t)row * SEQ;
    int tid = threadIdx.x;
    __shared__ float red[128];

    float m = -FLT_MAX;
    for (int j = i + tid; j < SEQ; j += 128) m = fmaxf(m, p[j]);
    red[tid] = m;
    __syncthreads();
    #pragma unroll
    for (int s = 64; s > 0; s >>= 1) {
        if (tid < s) red[tid] = fmaxf(red[tid], red[tid + s]);
        __syncthreads();
    }
    m = red[0];
    __syncthreads();

    float l = 0.f;
    for (int j = i + tid; j < SEQ; j += 128) l += __expf(p[j] - m);
    red[tid] = l;
    __syncthreads();
    #pragma unroll
    for (int s = 64; s > 0; s >>= 1) {
        if (tid < s) red[tid] += red[tid + s];
        __syncthreads();
    }
    if (tid == 0) {
        g_m[row]    = m;
        g_linv[row] = 1.0f / red[0];
    }
}

// ---------------------------------------------------------------------------
// Kernel 3: normalize weights (write final W), zero-fill masked tiles,
// and accumulate O[i,:] = sum_j w[i,j] * V[j,:]  (second tiled GEMM).
// ---------------------------------------------------------------------------
__global__ __launch_bounds__(256) void out_kernel(
    const float* __restrict__ Vg, float* __restrict__ W,
    float* __restrict__ O)
{
    int it = blockIdx.x;
    int b  = blockIdx.y;
    extern __shared__ float sm[];
    float* WsT = sm;              // [128][128] WsT[j][i] normalized weights
    float* Vs  = sm + 128 * 128;  // [128][128] Vs[j][d]

    int tid = threadIdx.x;
    int tx = tid & 15;   // d direction
    int ty = tid >> 4;   // i direction
    size_t Wbb = (size_t)b * SEQ * SEQ;

    // zero-fill tiles fully below the diagonal (j < i everywhere)
    float4 z4 = make_float4(0.f, 0.f, 0.f, 0.f);
    for (int jt = 0; jt < it; jt++) {
        #pragma unroll
        for (int k = 0; k < 16; k++) {
            int idx = tid + k * 256;
            int i  = idx & 127;
            int c4 = idx >> 7;
            *(float4*)(W + Wbb + (size_t)(it * 128 + i) * SEQ + jt * 128 + c4 * 4) = z4;
        }
    }

    float c[8][8];
    #pragma unroll
    for (int a = 0; a < 8; a++)
        #pragma unroll
        for (int bq = 0; bq < 8; bq++) c[a][bq] = 0.f;

    for (int jt = it; jt < TT; jt++) {
        __syncthreads();   // previous GEMM reads done before smem overwrite

        // read raw scores, normalize, write final weights, stage transposed
        #pragma unroll
        for (int k = 0; k < 16; k++) {
            int idx = tid + k * 256;
            int i  = idx & 127;
            int c4 = idx >> 7;
            int ig = it * 128 + i;
            float m    = g_m[b * SEQ + ig];
            float linv = g_linv[b * SEQ + ig];
            float* wp = W + Wbb + (size_t)ig * SEQ + jt * 128 + c4 * 4;
            float4 s = *(const float4*)wp;
            int jg = jt * 128 + c4 * 4;
            float4 w;
            w.x = (jg + 0 >= ig) ? __expf(s.x - m) * linv : 0.f;
            w.y = (jg + 1 >= ig) ? __expf(s.y - m) * linv : 0.f;
            w.z = (jg + 2 >= ig) ? __expf(s.z - m) * linv : 0.f;
            w.w = (jg + 3 >= ig) ? __expf(s.w - m) * linv : 0.f;
            *(float4*)wp = w;
            WsT[(c4 * 4 + 0) * 128 + i] = w.x;
            WsT[(c4 * 4 + 1) * 128 + i] = w.y;
            WsT[(c4 * 4 + 2) * 128 + i] = w.z;
            WsT[(c4 * 4 + 3) * 128 + i] = w.w;
        }
        // load V tile [j][d]
        #pragma unroll
        for (int k = 0; k < 16; k++) {
            int idx  = tid + k * 256;
            int jrow = idx >> 5;       // 0..127 over all k
            int c4   = idx & 31;
            float4 v = *(const float4*)(Vg + ((size_t)b * SEQ + jt * 128 + jrow) * HD + c4 * 4);
            *(float4*)(Vs + jrow * 128 + c4 * 4) = v;
        }
        __syncthreads();

        #pragma unroll 8
        for (int j = 0; j < 128; j++) {
            float4 a0 = *(const float4*)(WsT + j * 128 + ty * 4);
            float4 a1 = *(const float4*)(WsT + j * 128 + 64 + ty * 4);
            float4 b0 = *(const float4*)(Vs + j * 128 + tx * 4);
            float4 b1 = *(const float4*)(Vs + j * 128 + 64 + tx * 4);
            float av[8] = {a0.x, a0.y, a0.z, a0.w, a1.x, a1.y, a1.z, a1.w};
            float bv[8] = {b0.x, b0.y, b0.z, b0.w, b1.x, b1.y, b1.z, b1.w};
            #pragma unroll
            for (int ri = 0; ri < 8; ri++)
                #pragma unroll
                for (int rj = 0; rj < 8; rj++)
                    c[ri][rj] += av[ri] * bv[rj];
        }
    }

    // write O tile
    #pragma unroll
    for (int ri = 0; ri < 8; ri++) {
        int ig = it * 128 + ((ri < 4) ? (ty * 4 + ri) : (64 + ty * 4 + ri - 4));
        float* orow = O + ((size_t)b * SEQ + ig) * HD;
        *(float4*)(orow + tx * 4)      = make_float4(c[ri][0], c[ri][1], c[ri][2], c[ri][3]);
        *(float4*)(orow + 64 + tx * 4) = make_float4(c[ri][4], c[ri][5], c[ri][6], c[ri][7]);
    }
}

// ---------------------------------------------------------------------------
extern "C" void kernel_launch(void* const* d_in, const int* in_sizes, int n_in,
                              void* d_out, int out_size)
{
    const float* Q = (const float*)d_in[0];
    const float* K = (const float*)d_in[1];
    const float* V = (const float*)d_in[2];
    float* O = (float*)d_out;                              // [NB, SEQ, HD]
    float* W = (float*)d_out + (size_t)NB * SEQ * HD;      // [NB, SEQ, SEQ]

    // 128 KB dynamic smem per GEMM kernel (host attr call, not a stream op)
    cudaFuncSetAttribute(scores_kernel, cudaFuncAttributeMaxDynamicSharedMemorySize, 131072);
    cudaFuncSetAttribute(out_kernel,    cudaFuncAttributeMaxDynamicSharedMemorySize, 131072);

    scores_kernel<<<dim3(NPAIRS, NB), 256, 131072>>>(Q, K, W);
    stats_kernel<<<NB * SEQ, 128>>>(W);
    out_kernel<<<dim3(TT, NB), 256, 131072>>>(V, W, O);
}

// round 4
// speedup vs baseline: 1.1800x; 1.1800x over previous
#include <cuda_runtime.h>
#include <cfloat>
#include <cstdint>

constexpr int NB  = 16;
constexpr int SEQ = 2048;
constexpr int HD  = 128;
constexpr int TT  = SEQ / 128;            // 16
constexpr int NPAIRS = TT * (TT + 1) / 2; // 136
constexpr int CH  = 4;                    // j-tiles per PV chunk
constexpr int NCHUNK_PAIRS = 40;          // sum over it of ceil((TT-it)/CH)
#define SCALE 0.08838834764831845f

__device__ float g_m[NB * SEQ];
__device__ float g_linv[NB * SEQ];
// Partial O accumulators: [chunk][b][i][d], 64 MB static scratch
__device__ float g_part[(size_t)CH * NB * SEQ * HD];

// ---------------------------------------------------------------------------
// Kernel 1: raw scores. s[b,i,j] = (K_i . Q_j)*SCALE for tile pairs jt>=it.
// d is chunked 2x64 so smem = 64KB -> 2 CTAs/SM.
// ---------------------------------------------------------------------------
__global__ __launch_bounds__(256, 2) void scores_kernel(
    const float* __restrict__ Qg, const float* __restrict__ Kg,
    float* __restrict__ W)
{
    int t = blockIdx.x;
    int b = blockIdx.y;
    int it = 0;
    while (true) { int len = TT - it; if (t < len) break; t -= len; ++it; }
    int jt = it + t;

    extern __shared__ float sm[];
    float* As = sm;             // [64][128]  As[d_local][i] (K tile slice, transposed)
    float* Bs = sm + 64 * 128;  // [64][128]  Bs[d_local][j] (Q tile slice, transposed)

    int tid = threadIdx.x;
    const float* Kbase = Kg + ((size_t)b * SEQ + (size_t)it * 128) * HD;
    const float* Qbase = Qg + ((size_t)b * SEQ + (size_t)jt * 128) * HD;

    int tx = tid & 15;
    int ty = tid >> 4;
    float c[8][8];
    #pragma unroll
    for (int a = 0; a < 8; a++)
        #pragma unroll
        for (int q = 0; q < 8; q++) c[a][q] = 0.f;

    #pragma unroll
    for (int ch = 0; ch < 2; ch++) {
        __syncthreads();
        // load 128 rows x 64 d-values of each operand, transposed
        #pragma unroll
        for (int k = 0; k < 8; k++) {
            int idx = tid + k * 256;        // 0..2047
            int row = idx & 127;
            int c4l = idx >> 7;             // 0..15
            float4 kv = *(const float4*)(Kbase + row * HD + ch * 64 + c4l * 4);
            float4 qv = *(const float4*)(Qbase + row * HD + ch * 64 + c4l * 4);
            As[(c4l * 4 + 0) * 128 + row] = kv.x;
            As[(c4l * 4 + 1) * 128 + row] = kv.y;
            As[(c4l * 4 + 2) * 128 + row] = kv.z;
            As[(c4l * 4 + 3) * 128 + row] = kv.w;
            Bs[(c4l * 4 + 0) * 128 + row] = qv.x;
            Bs[(c4l * 4 + 1) * 128 + row] = qv.y;
            Bs[(c4l * 4 + 2) * 128 + row] = qv.z;
            Bs[(c4l * 4 + 3) * 128 + row] = qv.w;
        }
        __syncthreads();

        #pragma unroll 8
        for (int d = 0; d < 64; d++) {
            float4 a0 = *(const float4*)(As + d * 128 + ty * 4);
            float4 a1 = *(const float4*)(As + d * 128 + 64 + ty * 4);
            float4 b0 = *(const float4*)(Bs + d * 128 + tx * 4);
            float4 b1 = *(const float4*)(Bs + d * 128 + 64 + tx * 4);
            float av[8] = {a0.x, a0.y, a0.z, a0.w, a1.x, a1.y, a1.z, a1.w};
            float bv[8] = {b0.x, b0.y, b0.z, b0.w, b1.x, b1.y, b1.z, b1.w};
            #pragma unroll
            for (int ri = 0; ri < 8; ri++)
                #pragma unroll
                for (int rj = 0; rj < 8; rj++)
                    c[ri][rj] += av[ri] * bv[rj];
        }
    }

    size_t Wbb = (size_t)b * SEQ * SEQ;
    #pragma unroll
    for (int ri = 0; ri < 8; ri++) {
        int i = it * 128 + ((ri < 4) ? (ty * 4 + ri) : (64 + ty * 4 + ri - 4));
        float* wrow = W + Wbb + (size_t)i * SEQ + jt * 128;
        *(float4*)(wrow + tx * 4) =
            make_float4(c[ri][0] * SCALE, c[ri][1] * SCALE, c[ri][2] * SCALE, c[ri][3] * SCALE);
        *(float4*)(wrow + 64 + tx * 4) =
            make_float4(c[ri][4] * SCALE, c[ri][5] * SCALE, c[ri][6] * SCALE, c[ri][7] * SCALE);
    }
}

// ---------------------------------------------------------------------------
// Kernel 2: per-row softmax stats over j in [i, SEQ).
// ---------------------------------------------------------------------------
__global__ __launch_bounds__(128) void stats_kernel(const float* __restrict__ W)
{
    int row = blockIdx.x;            // b*SEQ + i
    int i = row & (SEQ - 1);
    const float* p = W + (size_t)row * SEQ;
    int tid = threadIdx.x;
    __shared__ float red[128];

    float m = -FLT_MAX;
    for (int j = i + tid; j < SEQ; j += 128) m = fmaxf(m, p[j]);
    red[tid] = m;
    __syncthreads();
    #pragma unroll
    for (int s = 64; s > 0; s >>= 1) {
        if (tid < s) red[tid] = fmaxf(red[tid], red[tid + s]);
        __syncthreads();
    }
    m = red[0];
    __syncthreads();

    float l = 0.f;
    for (int j = i + tid; j < SEQ; j += 128) l += __expf(p[j] - m);
    red[tid] = l;
    __syncthreads();
    #pragma unroll
    for (int s = 64; s > 0; s >>= 1) {
        if (tid < s) red[tid] += red[tid + s];
        __syncthreads();
    }
    if (tid == 0) {
        g_m[row]    = m;
        g_linv[row] = 1.0f / red[0];
    }
}

// ---------------------------------------------------------------------------
// Kernel 3: zero-fill fully-masked tiles (jt < it) of W.
// ---------------------------------------------------------------------------
__global__ __launch_bounds__(256) void zero_fill_kernel(float* __restrict__ W)
{
    int it = blockIdx.x;
    int b  = blockIdx.y;
    if (it == 0) return;
    size_t base = (size_t)b * SEQ * SEQ + (size_t)it * 128 * SEQ;
    int cols4 = it * 32;                 // float4s per row in [0, it*128)
    int total = 128 * cols4;
    float4 z = make_float4(0.f, 0.f, 0.f, 0.f);
    for (int v = threadIdx.x; v < total; v += 256) {
        int row  = v / cols4;
        int col4 = v - row * cols4;
        *(float4*)(W + base + (size_t)row * SEQ + col4 * 4) = z;
    }
}

// ---------------------------------------------------------------------------
// Kernel 4: chunked PV GEMM with fused normalize.
// Each CTA = (it, chunk): normalizes + writes final W for its j-tiles,
// accumulates partial O tile into g_part[chunk].
// ---------------------------------------------------------------------------
__global__ __launch_bounds__(256) void pv_kernel(
    const float* __restrict__ Vg, float* __restrict__ W)
{
    int t = blockIdx.x;
    int b = blockIdx.y;
    int it = 0;
    while (true) { int nc = (TT - it + CH - 1) / CH; if (t < nc) break; t -= nc; ++it; }
    int chunk = t;
    int jt_begin = it + chunk * CH;
    int jt_end   = min(jt_begin + CH, TT);

    extern __shared__ float sm[];
    float* WsT = sm;              // [128][128] WsT[j_local][i]
    float* Vs  = sm + 128 * 128;  // [128][128] Vs[j_local][d]

    int tid = threadIdx.x;
    int tx = tid & 15;   // d
    int ty = tid >> 4;   // i
    size_t Wbb = (size_t)b * SEQ * SEQ;

    float c[8][8];
    #pragma unroll
    for (int a = 0; a < 8; a++)
        #pragma unroll
        for (int q = 0; q < 8; q++) c[a][q] = 0.f;

    for (int jt = jt_begin; jt < jt_end; jt++) {
        __syncthreads();

        // normalize raw scores -> final weights, stage transposed
        #pragma unroll
        for (int k = 0; k < 16; k++) {
            int idx = tid + k * 256;
            int i  = idx & 127;
            int c4 = idx >> 7;
            int ig = it * 128 + i;
            float m    = g_m[b * SEQ + ig];
            float linv = g_linv[b * SEQ + ig];
            float* wp = W + Wbb + (size_t)ig * SEQ + jt * 128 + c4 * 4;
            float4 s = *(const float4*)wp;
            int jg = jt * 128 + c4 * 4;
            float4 w;
            w.x = (jg + 0 >= ig) ? __expf(s.x - m) * linv : 0.f;
            w.y = (jg + 1 >= ig) ? __expf(s.y - m) * linv : 0.f;
            w.z = (jg + 2 >= ig) ? __expf(s.z - m) * linv : 0.f;
            w.w = (jg + 3 >= ig) ? __expf(s.w - m) * linv : 0.f;
            *(float4*)wp = w;
            WsT[(c4 * 4 + 0) * 128 + i] = w.x;
            WsT[(c4 * 4 + 1) * 128 + i] = w.y;
            WsT[(c4 * 4 + 2) * 128 + i] = w.z;
            WsT[(c4 * 4 + 3) * 128 + i] = w.w;
        }
        // load V tile [j][d]
        #pragma unroll
        for (int k = 0; k < 16; k++) {
            int idx  = tid + k * 256;
            int jrow = idx >> 5;
            int c4   = idx & 31;
            float4 v = *(const float4*)(Vg + ((size_t)b * SEQ + jt * 128 + jrow) * HD + c4 * 4);
            *(float4*)(Vs + jrow * 128 + c4 * 4) = v;
        }
        __syncthreads();

        #pragma unroll 8
        for (int j = 0; j < 128; j++) {
            float4 a0 = *(const float4*)(WsT + j * 128 + ty * 4);
            float4 a1 = *(const float4*)(WsT + j * 128 + 64 + ty * 4);
            float4 b0 = *(const float4*)(Vs + j * 128 + tx * 4);
            float4 b1 = *(const float4*)(Vs + j * 128 + 64 + tx * 4);
            float av[8] = {a0.x, a0.y, a0.z, a0.w, a1.x, a1.y, a1.z, a1.w};
            float bv[8] = {b0.x, b0.y, b0.z, b0.w, b1.x, b1.y, b1.z, b1.w};
            #pragma unroll
            for (int ri = 0; ri < 8; ri++)
                #pragma unroll
                for (int rj = 0; rj < 8; rj++)
                    c[ri][rj] += av[ri] * bv[rj];
        }
    }

    // write partial O tile to scratch
    float* pbase = g_part + (((size_t)chunk * NB + b) * SEQ) * HD;
    #pragma unroll
    for (int ri = 0; ri < 8; ri++) {
        int ig = it * 128 + ((ri < 4) ? (ty * 4 + ri) : (64 + ty * 4 + ri - 4));
        float* prow = pbase + (size_t)ig * HD;
        *(float4*)(prow + tx * 4)      = make_float4(c[ri][0], c[ri][1], c[ri][2], c[ri][3]);
        *(float4*)(prow + 64 + tx * 4) = make_float4(c[ri][4], c[ri][5], c[ri][6], c[ri][7]);
    }
}

// ---------------------------------------------------------------------------
// Kernel 5: reduce partials into O.
// ---------------------------------------------------------------------------
__global__ __launch_bounds__(256) void reduce_kernel(float* __restrict__ O)
{
    int idx = blockIdx.x * 256 + threadIdx.x;     // float4 index
    size_t base = (size_t)idx * 4;
    int row = (int)(base >> 7);                   // b*SEQ + i
    int i   = row & (SEQ - 1);
    int it  = i >> 7;
    int nc  = (TT - it + CH - 1) / CH;

    float4 acc = make_float4(0.f, 0.f, 0.f, 0.f);
    for (int cix = 0; cix < nc; cix++) {
        const float4 p = *(const float4*)(g_part + (size_t)cix * NB * SEQ * HD + base);
        acc.x += p.x; acc.y += p.y; acc.z += p.z; acc.w += p.w;
    }
    *(float4*)(O + base) = acc;
}

// ---------------------------------------------------------------------------
extern "C" void kernel_launch(void* const* d_in, const int* in_sizes, int n_in,
                              void* d_out, int out_size)
{
    const float* Q = (const float*)d_in[0];
    const float* K = (const float*)d_in[1];
    const float* V = (const float*)d_in[2];
    float* O = (float*)d_out;                              // [NB, SEQ, HD]
    float* W = (float*)d_out + (size_t)NB * SEQ * HD;      // [NB, SEQ, SEQ]

    cudaFuncSetAttribute(scores_kernel, cudaFuncAttributeMaxDynamicSharedMemorySize, 65536);
    cudaFuncSetAttribute(pv_kernel,     cudaFuncAttributeMaxDynamicSharedMemorySize, 131072);

    scores_kernel<<<dim3(NPAIRS, NB), 256, 65536>>>(Q, K, W);
    stats_kernel<<<NB * SEQ, 128>>>(W);
    zero_fill_kernel<<<dim3(TT, NB), 256>>>(W);
    pv_kernel<<<dim3(NCHUNK_PAIRS, NB), 256, 131072>>>(V, W);
    reduce_kernel<<<(NB * SEQ * HD / 4) / 256, 256>>>(O);
}

// round 13
// speedup vs baseline: 3.8650x; 3.2755x over previous
#include <cuda_runtime.h>
#include <cuda_bf16.h>
#include <cfloat>
#include <cstdint>

constexpr int NB  = 16;
constexpr int SEQ = 2048;
constexpr int HD  = 128;
constexpr int TT  = SEQ / 128;            // 16
constexpr int NPAIRS = TT * (TT + 1) / 2; // 136
constexpr int CH  = 4;                    // j-tiles per PV chunk
constexpr int NCHUNK_PAIRS = 40;          // sum over it of ceil((TT-it)/CH)
#define SCALE 0.08838834764831845f

__device__ float g_m[NB * SEQ];
__device__ float g_linv[NB * SEQ];
__device__ float g_part[(size_t)CH * NB * SEQ * HD];   // 64 MB scratch

// ---------------- smem layouts (dynamic, byte offsets) ----------------
// scores: A=K tile, B=Q tile; 128 rows x 64 bf16 + 8 pad -> 144B stride
constexpr int SA_STRIDE = 144;
constexpr int OFF_AH = 0;
constexpr int OFF_AL = 18432;
constexpr int OFF_BH = 36864;
constexpr int OFF_BL = 55296;
constexpr int SMEM_BYTES = 73728;
// pv: W tile 128 rows x 64 bf16 (144B stride); V tile 64 rows x 128 bf16 + 8 pad (272B)
constexpr int OFF_WH = 0;
constexpr int OFF_WL = 18432;
constexpr int SV_STRIDE = 272;
constexpr int OFF_VH = 36864;
constexpr int OFF_VL = 54272;

// ---------------- helpers ----------------
__device__ __forceinline__ uint32_t smem_u32(const void* p) {
    uint32_t a;
    asm("{ .reg .u64 t; cvta.to.shared.u64 t, %1; cvt.u32.u64 %0, t; }"
        : "=r"(a) : "l"(p));
    return a;
}
__device__ __forceinline__ void ldm_x4(uint32_t* r, uint32_t addr) {
    asm volatile("ldmatrix.sync.aligned.m8n8.x4.shared.b16 {%0,%1,%2,%3}, [%4];"
        : "=r"(r[0]), "=r"(r[1]), "=r"(r[2]), "=r"(r[3]) : "r"(addr));
}
__device__ __forceinline__ void ldm_x4_t(uint32_t* r, uint32_t addr) {
    asm volatile("ldmatrix.sync.aligned.m8n8.x4.trans.shared.b16 {%0,%1,%2,%3}, [%4];"
        : "=r"(r[0]), "=r"(r[1]), "=r"(r[2]), "=r"(r[3]) : "r"(addr));
}
__device__ __forceinline__ void mma16816(float* d, const uint32_t* a, const uint32_t* b) {
    asm volatile(
        "mma.sync.aligned.m16n8k16.row.col.f32.bf16.bf16.f32 "
        "{%0,%1,%2,%3}, {%4,%5,%6,%7}, {%8,%9}, {%0,%1,%2,%3};"
        : "+f"(d[0]), "+f"(d[1]), "+f"(d[2]), "+f"(d[3])
        : "r"(a[0]), "r"(a[1]), "r"(a[2]), "r"(a[3]), "r"(b[0]), "r"(b[1]));
}
__device__ __forceinline__ void split2(float x, unsigned short& h, unsigned short& l) {
    __nv_bfloat16 hb = __float2bfloat16(x);
    __nv_bfloat16 lb = __float2bfloat16(x - __bfloat162float(hb));
    h = __bfloat16_as_ushort(hb);
    l = __bfloat16_as_ushort(lb);
}
__device__ __forceinline__ void store_split(char* ph, char* pl, float4 v) {
    unsigned short h0,h1,h2,h3,l0,l1,l2,l3;
    split2(v.x,h0,l0); split2(v.y,h1,l1); split2(v.z,h2,l2); split2(v.w,h3,l3);
    *(uint2*)ph = make_uint2((uint32_t)h0 | ((uint32_t)h1 << 16),
                             (uint32_t)h2 | ((uint32_t)h3 << 16));
    *(uint2*)pl = make_uint2((uint32_t)l0 | ((uint32_t)l1 << 16),
                             (uint32_t)l2 | ((uint32_t)l3 << 16));
}

// ---------------------------------------------------------------------------
// Kernel 1: raw scores via HMMA bf16x3.  s[b,i,j] = (K_i.Q_j)*SCALE, jt>=it.
// ---------------------------------------------------------------------------
__global__ __launch_bounds__(256, 2) void scores_kernel(
    const float* __restrict__ Qg, const float* __restrict__ Kg,
    float* __restrict__ Wg)
{
    int t = blockIdx.x, b = blockIdx.y;
    int it = 0;
    while (true) { int len = TT - it; if (t < len) break; t -= len; ++it; }
    int jt = it + t;

    extern __shared__ char smc[];
    uint32_t sb = smem_u32(smc);
    int tid = threadIdx.x, wid = tid >> 5, lane = tid & 31;
    int m_base = (wid & 3) * 32, n_base = (wid >> 2) * 64;

    const float* Kb = Kg + ((size_t)b * SEQ + (size_t)it * 128) * HD;
    const float* Qb = Qg + ((size_t)b * SEQ + (size_t)jt * 128) * HD;

    float acc[2][8][4];
    #pragma unroll
    for (int mt = 0; mt < 2; mt++)
        #pragma unroll
        for (int nt = 0; nt < 8; nt++)
            #pragma unroll
            for (int e = 0; e < 4; e++) acc[mt][nt][e] = 0.f;

    #pragma unroll
    for (int ch = 0; ch < 2; ch++) {
        __syncthreads();
        #pragma unroll
        for (int k = 0; k < 8; k++) {
            int idx = tid + k * 256;
            int r = idx >> 4, c4 = idx & 15;
            float4 kv = *(const float4*)(Kb + r * HD + ch * 64 + c4 * 4);
            float4 qv = *(const float4*)(Qb + r * HD + ch * 64 + c4 * 4);
            store_split(smc + OFF_AH + r * SA_STRIDE + c4 * 8,
                        smc + OFF_AL + r * SA_STRIDE + c4 * 8, kv);
            store_split(smc + OFF_BH + r * SA_STRIDE + c4 * 8,
                        smc + OFF_BL + r * SA_STRIDE + c4 * 8, qv);
        }
        __syncthreads();

        int arow = lane & 15, akg = lane >> 4;
        int nrow = (lane & 7) + ((lane & 16) >> 1);
        int bkg  = (lane >> 3) & 1;
        #pragma unroll
        for (int p = 0; p < 3; p++) {
            uint32_t aO = sb + ((p == 2) ? OFF_AL : OFF_AH);
            uint32_t bO = sb + ((p == 1) ? OFF_BL : OFF_BH);
            #pragma unroll
            for (int ks = 0; ks < 4; ks++) {
                uint32_t a[2][4];
                ldm_x4(a[0], aO + (m_base + arow) * SA_STRIDE + (ks * 16 + akg * 8) * 2);
                ldm_x4(a[1], aO + (m_base + 16 + arow) * SA_STRIDE + (ks * 16 + akg * 8) * 2);
                #pragma unroll
                for (int ntp = 0; ntp < 4; ntp++) {
                    uint32_t bf[4];
                    ldm_x4(bf, bO + (n_base + ntp * 16 + nrow) * SA_STRIDE + (ks * 16 + bkg * 8) * 2);
                    #pragma unroll
                    for (int mt = 0; mt < 2; mt++) {
                        mma16816(acc[mt][ntp * 2],     a[mt], bf);
                        mma16816(acc[mt][ntp * 2 + 1], a[mt], bf + 2);
                    }
                }
            }
        }
    }

    // epilogue: write raw scaled scores
    size_t Wbb = (size_t)b * SEQ * SEQ;
    int r0 = lane >> 2, c0 = (lane & 3) * 2;
    #pragma unroll
    for (int mt = 0; mt < 2; mt++) {
        #pragma unroll
        for (int nt = 0; nt < 8; nt++) {
            int i0 = it * 128 + m_base + mt * 16 + r0;
            int j  = jt * 128 + n_base + nt * 8 + c0;
            float* p0 = Wg + Wbb + (size_t)i0 * SEQ + j;
            *(float2*)p0 = make_float2(acc[mt][nt][0] * SCALE, acc[mt][nt][1] * SCALE);
            *(float2*)(p0 + (size_t)8 * SEQ) =
                make_float2(acc[mt][nt][2] * SCALE, acc[mt][nt][3] * SCALE);
        }
    }
}

// ---------------------------------------------------------------------------
// Kernel 2: per-row softmax stats over j in [i, SEQ).
// ---------------------------------------------------------------------------
__global__ __launch_bounds__(128) void stats_kernel(const float* __restrict__ W)
{
    int row = blockIdx.x;            // b*SEQ + i
    int i = row & (SEQ - 1);
    const float* p = W + (size_t)row * SEQ;
    int tid = threadIdx.x;
    __shared__ float red[128];

    float m = -FLT_MAX;
    for (int j = i + tid; j < SEQ; j += 128) m = fmaxf(m, p[j]);
    red[tid] = m;
    __syncthreads();
    #pragma unroll
    for (int s = 64; s > 0; s >>= 1) {
        if (tid < s) red[tid] = fmaxf(red[tid], red[tid + s]);
        __syncthreads();
    }
    m = red[0];
    __syncthreads();

    float l = 0.f;
    for (int j = i + tid; j < SEQ; j += 128) l += __expf(p[j] - m);
    red[tid] = l;
    __syncthreads();
    #pragma unroll
    for (int s = 64; s > 0; s >>= 1) {
        if (tid < s) red[tid] += red[tid + s];
        __syncthreads();
    }
    if (tid == 0) {
        g_m[row]    = m;
        g_linv[row] = 1.0f / red[0];
    }
}

// ---------------------------------------------------------------------------
// Kernel 3: zero-fill fully-masked tiles (jt < it) of W.
// ---------------------------------------------------------------------------
__global__ __launch_bounds__(256) void zero_fill_kernel(float* __restrict__ W)
{
    int it = blockIdx.x;
    int b  = blockIdx.y;
    if (it == 0) return;
    size_t base = (size_t)b * SEQ * SEQ + (size_t)it * 128 * SEQ;
    int cols4 = it * 32;
    int total = 128 * cols4;
    float4 z = make_float4(0.f, 0.f, 0.f, 0.f);
    for (int v = threadIdx.x; v < total; v += 256) {
        int row  = v / cols4;
        int col4 = v - row * cols4;
        *(float4*)(W + base + (size_t)row * SEQ + col4 * 4) = z;
    }
}

// ---------------------------------------------------------------------------
// Kernel 4: chunked PV via HMMA bf16x3 with fused normalize + final-W write.
// ---------------------------------------------------------------------------
__global__ __launch_bounds__(256, 2) void pv_kernel(
    const float* __restrict__ Vg, float* __restrict__ Wg)
{
    int t = blockIdx.x, b = blockIdx.y;
    int it = 0;
    while (true) { int nc = (TT - it + CH - 1) / CH; if (t < nc) break; t -= nc; ++it; }
    int chunk = t;
    int jt_begin = it + chunk * CH;
    int jt_end   = min(jt_begin + CH, TT);

    extern __shared__ char smc[];
    uint32_t sb = smem_u32(smc);
    int tid = threadIdx.x, wid = tid >> 5, lane = tid & 31;
    int m_base = (wid & 3) * 32, n_base = (wid >> 2) * 64;   // n = d
    size_t Wbb = (size_t)b * SEQ * SEQ;

    float acc[2][8][4];
    #pragma unroll
    for (int mt = 0; mt < 2; mt++)
        #pragma unroll
        for (int nt = 0; nt < 8; nt++)
            #pragma unroll
            for (int e = 0; e < 4; e++) acc[mt][nt][e] = 0.f;

    for (int jt = jt_begin; jt < jt_end; jt++) {
        #pragma unroll
        for (int kc = 0; kc < 2; kc++) {
            __syncthreads();
            // stage normalized W (cols kc*64..+64), write final W to gmem
            #pragma unroll
            for (int k = 0; k < 8; k++) {
                int idx = tid + k * 256;
                int r = idx >> 4, c4 = idx & 15;
                int ig = it * 128 + r;
                int jg = jt * 128 + kc * 64 + c4 * 4;
                float mm = g_m[b * SEQ + ig];
                float li = g_linv[b * SEQ + ig];
                float* wp = Wg + Wbb + (size_t)ig * SEQ + jg;
                float4 s = *(const float4*)wp;
                float4 w;
                w.x = (jg + 0 >= ig) ? __expf(s.x - mm) * li : 0.f;
                w.y = (jg + 1 >= ig) ? __expf(s.y - mm) * li : 0.f;
                w.z = (jg + 2 >= ig) ? __expf(s.z - mm) * li : 0.f;
                w.w = (jg + 3 >= ig) ? __expf(s.w - mm) * li : 0.f;
                *(float4*)wp = w;
                store_split(smc + OFF_WH + r * SA_STRIDE + c4 * 8,
                            smc + OFF_WL + r * SA_STRIDE + c4 * 8, w);
            }
            // stage V rows [jt*128+kc*64, +64), row-major [j][d]
            const float* Vb = Vg + ((size_t)b * SEQ + (size_t)jt * 128 + kc * 64) * HD;
            #pragma unroll
            for (int k = 0; k < 8; k++) {
                int idx = tid + k * 256;
                int r = idx >> 5, c4 = idx & 31;
                float4 v = *(const float4*)(Vb + r * HD + c4 * 4);
                store_split(smc + OFF_VH + r * SV_STRIDE + c4 * 8,
                            smc + OFF_VL + r * SV_STRIDE + c4 * 8, v);
            }
            __syncthreads();

            int arow = lane & 15, akg = lane >> 4;
            int jrow = (lane & 7) + (lane & 8);     // trans-B source row (k = j)
            int dcol = (lane >> 4) * 8;
            #pragma unroll
            for (int p = 0; p < 3; p++) {
                uint32_t aO = sb + ((p == 2) ? OFF_WL : OFF_WH);
                uint32_t bO = sb + ((p == 1) ? OFF_VL : OFF_VH);
                #pragma unroll
                for (int ks = 0; ks < 4; ks++) {
                    uint32_t a[2][4];
                    ldm_x4(a[0], aO + (m_base + arow) * SA_STRIDE + (ks * 16 + akg * 8) * 2);
                    ldm_x4(a[1], aO + (m_base + 16 + arow) * SA_STRIDE + (ks * 16 + akg * 8) * 2);
                    #pragma unroll
                    for (int ntp = 0; ntp < 4; ntp++) {
                        uint32_t bf[4];
                        ldm_x4_t(bf, bO + (ks * 16 + jrow) * SV_STRIDE
                                      + (n_base + ntp * 16 + dcol) * 2);
                        #pragma unroll
                        for (int mt = 0; mt < 2; mt++) {
                            mma16816(acc[mt][ntp * 2],     a[mt], bf);
                            mma16816(acc[mt][ntp * 2 + 1], a[mt], bf + 2);
                        }
                    }
                }
            }
        }
    }

    // write partial O tile
    float* pb = g_part + (((size_t)chunk * NB + b) * SEQ) * HD;
    int r0 = lane >> 2, c0 = (lane & 3) * 2;
    #pragma unroll
    for (int mt = 0; mt < 2; mt++) {
        #pragma unroll
        for (int nt = 0; nt < 8; nt++) {
            int i0 = it * 128 + m_base + mt * 16 + r0;
            int d  = n_base + nt * 8 + c0;
            *(float2*)(pb + (size_t)i0 * HD + d) =
                make_float2(acc[mt][nt][0], acc[mt][nt][1]);
            *(float2*)(pb + (size_t)(i0 + 8) * HD + d) =
                make_float2(acc[mt][nt][2], acc[mt][nt][3]);
        }
    }
}

// ---------------------------------------------------------------------------
// Kernel 5: reduce partials into O.
// ---------------------------------------------------------------------------
__global__ __launch_bounds__(256) void reduce_kernel(float* __restrict__ O)
{
    int idx = blockIdx.x * 256 + threadIdx.x;
    size_t base = (size_t)idx * 4;
    int row = (int)(base >> 7);
    int i   = row & (SEQ - 1);
    int it  = i >> 7;
    int nc  = (TT - it + CH - 1) / CH;

    float4 acc = make_float4(0.f, 0.f, 0.f, 0.f);
    for (int cix = 0; cix < nc; cix++) {
        const float4 p = *(const float4*)(g_part + (size_t)cix * NB * SEQ * HD + base);
        acc.x += p.x; acc.y += p.y; acc.z += p.z; acc.w += p.w;
    }
    *(float4*)(O + base) = acc;
}

// ---------------------------------------------------------------------------
extern "C" void kernel_launch(void* const* d_in, const int* in_sizes, int n_in,
                              void* d_out, int out_size)
{
    const float* Q = (const float*)d_in[0];
    const float* K = (const float*)d_in[1];
    const float* V = (const float*)d_in[2];
    float* O = (float*)d_out;                              // [NB, SEQ, HD]
    float* W = (float*)d_out + (size_t)NB * SEQ * HD;      // [NB, SEQ, SEQ]

    cudaFuncSetAttribute(scores_kernel, cudaFuncAttributeMaxDynamicSharedMemorySize, SMEM_BYTES);
    cudaFuncSetAttribute(pv_kernel,     cudaFuncAttributeMaxDynamicSharedMemorySize, SMEM_BYTES);

    scores_kernel<<<dim3(NPAIRS, NB), 256, SMEM_BYTES>>>(Q, K, W);
    stats_kernel<<<NB * SEQ, 128>>>(W);
    zero_fill_kernel<<<dim3(TT, NB), 256>>>(W);
    pv_kernel<<<dim3(NCHUNK_PAIRS, NB), 256, SMEM_BYTES>>>(V, W);
    reduce_kernel<<<(NB * SEQ * HD / 4) / 256, 256>>>(O);
}